// round 13
// baseline (speedup 1.0000x reference)
#include <cuda_runtime.h>

#define N_NODES 2048
#define N_EDGES 4096
#define FV 64
#define FE 16
#define NH 128
#define NC 128

#define ELLW 40
#define MAXPAR 4

// ---------------- scratch (device globals; no allocation) ----------------
__device__ float g_Y[N_NODES * NH];
__device__ float g_tmpN[N_NODES * NH];
__device__ float g_X1F1[N_NODES * 2 * NH];
__device__ float g_X3[N_NODES * NH];
__device__ float g_Yh[N_EDGES * FE];
__device__ float g_Z2F2[N_EDGES * 2 * FE];
__device__ float g_Z4[N_EDGES * FE];

// gates: all DIRECT-WRITE (split by producer; consumers sum)
__device__ float g_se1[N_EDGES];
__device__ float g_se3a[N_EDGES];   // from mlp2 (F2 part)
__device__ float g_se3b[N_EDGES];   // from spmm2 (Z2 part)
__device__ float g_se5[N_EDGES];
__device__ float g_sn2a[N_NODES];   // from LN/F1
__device__ float g_sn2b[N_NODES];   // from spmm1/X1
__device__ float g_sn4[N_NODES];

// adj_v ELL (unordered)
__device__ int   g_vn[N_NODES];
__device__ int   g_vcol[N_NODES * ELLW];
__device__ float g_vval[N_NODES * ELLW];
__device__ int   g_scnt[N_NODES * ELLW];
__device__ int   g_eid[N_NODES * ELLW * MAXPAR];

// adj_e ELL (unordered)
__device__ int      g_en[N_EDGES];
__device__ int      g_ecol[N_EDGES * ELLW];
__device__ float    g_eval[N_EDGES * ELLW];
__device__ float    g_cA[N_EDGES * ELLW];
__device__ float    g_cB[N_EDGES * ELLW];
__device__ float    g_cC[N_EDGES * ELLW];
__device__ float    g_adjEv[N_EDGES * ELLW];
__device__ unsigned g_cmax2[N_EDGES];
__device__ unsigned g_cmax4[N_EDGES];

// edge endpoints from T
__device__ int   g_Ea[N_EDGES];
__device__ int   g_Eb[N_EDGES];
__device__ float g_Ewa[N_EDGES];
__device__ float g_Ewb[N_EDGES];
__device__ int   g_Ecnt[N_EDGES];

// ================= device helpers =================

// register-B GEMM tile: rows [rowBase, rowBase+16) x 128 cols of C = A[.,K] @ B[K,128]
// If doLN: instead of writing C, apply layernorm(g,b)+relu per row, write to lnOut
// (ld 256) and write gate dot with pg[128..255] into g_sn2a[row].
template <int DO_LN>
__device__ __forceinline__ void dev_gemm_rb(const float* __restrict__ A,
                                            const float* __restrict__ B,
                                            float* __restrict__ C, int K, int rowBase,
                                            const float* __restrict__ g,
                                            const float* __restrict__ b,
                                            const float* __restrict__ pg,
                                            float* __restrict__ lnOut,
                                            float* sh) {
    int col = threadIdx.x & 127;
    int half = threadIdx.x >> 7;
    float acc[8];
#pragma unroll
    for (int r = 0; r < 8; r++) acc[r] = 0.f;
    for (int kc = 0; kc < K; kc += 64) {
        float breg[64];
#pragma unroll
        for (int k = 0; k < 64; k++) breg[k] = B[(size_t)(kc + k) * 128 + col];
#pragma unroll
        for (int r = 0; r < 8; r++) {
            int row = rowBase + r * 2 + half;
            const float4* a4 = (const float4*)(A + (size_t)row * K + kc);
            float s = 0.f;
#pragma unroll
            for (int k4 = 0; k4 < 16; k4++) {
                float4 a = a4[k4];
                s += a.x * breg[4 * k4 + 0];
                s += a.y * breg[4 * k4 + 1];
                s += a.z * breg[4 * k4 + 2];
                s += a.w * breg[4 * k4 + 3];
            }
            acc[r] += s;
        }
    }
    if (!DO_LN) {
#pragma unroll
        for (int r = 0; r < 8; r++)
            C[(size_t)(rowBase + r * 2 + half) * 128 + col] = acc[r];
    } else {
        // stage 16 rows x 128 cols into smem, then warp-per-2-rows layernorm
#pragma unroll
        for (int r = 0; r < 8; r++)
            sh[(r * 2 + half) * 128 + col] = acc[r];
        __syncthreads();
        int warp = threadIdx.x >> 5;
        int lane = threadIdx.x & 31;
        for (int rr = warp; rr < 16; rr += 8) {
            const float* rowp = sh + rr * 128;
            float v[4];
            float sum = 0.f;
#pragma unroll
            for (int i = 0; i < 4; i++) { v[i] = rowp[lane + 32 * i]; sum += v[i]; }
            for (int o = 16; o; o >>= 1) sum += __shfl_xor_sync(0xffffffffu, sum, o);
            float mean = sum * (1.f / 128.f);
            float var = 0.f;
#pragma unroll
            for (int i = 0; i < 4; i++) { float d = v[i] - mean; var += d * d; }
            for (int o = 16; o; o >>= 1) var += __shfl_xor_sync(0xffffffffu, var, o);
            float rstd = rsqrtf(var * (1.f / 128.f) + 1e-5f);
            int row = rowBase + rr;
            float dotp = 0.f;
#pragma unroll
            for (int i = 0; i < 4; i++) {
                int idx = lane + 32 * i;
                float y = fmaxf((v[i] - mean) * rstd * g[idx] + b[idx], 0.f);
                lnOut[(size_t)row * 256 + idx] = y;
                dotp += y * pg[128 + idx];
            }
            for (int o = 16; o; o >>= 1) dotp += __shfl_xor_sync(0xffffffffu, dotp, o);
            if (lane == 0) g_sn2a[row] = dotp;
        }
    }
}

// fused edge MLP (layer 2): Yh=relu(Z)@W2, F2=relu(LN(Z@Wf2)), se1, se3a
__device__ __forceinline__ void dev_mlp2(const float* __restrict__ Z,
                                         const float* __restrict__ W2,
                                         const float* __restrict__ Wf2,
                                         const float* __restrict__ g2,
                                         const float* __restrict__ be2,
                                         const float* __restrict__ p1,
                                         const float* __restrict__ p3,
                                         int rowBase, float* sh) {
    float* sW = sh;
    float* sF = sh + 256;
    int tid = threadIdx.x;
    sW[tid] = W2[tid];
    sF[tid] = Wf2[tid];
    __syncthreads();
    int c = tid & 15;
    int r = rowBase + (tid >> 4);
    float zc = Z[(size_t)r * 16 + c];
    float a1 = 0.f, a2 = 0.f;
#pragma unroll
    for (int k = 0; k < 16; k++) {
        float zk = __shfl_sync(0xffffffffu, zc, k, 16);
        a1 += fmaxf(zk, 0.f) * sW[k * 16 + c];
        a2 += zk * sF[k * 16 + c];
    }
    g_Yh[(size_t)r * 16 + c] = a1;
    float d1 = zc * p1[c];
    for (int o = 8; o; o >>= 1) d1 += __shfl_xor_sync(0xffffffffu, d1, o, 16);
    if (c == 0) g_se1[r] = d1;
    float sum = a2;
    for (int o = 8; o; o >>= 1) sum += __shfl_xor_sync(0xffffffffu, sum, o, 16);
    float mean = sum * (1.f / 16.f);
    float d = a2 - mean;
    float var = d * d;
    for (int o = 8; o; o >>= 1) var += __shfl_xor_sync(0xffffffffu, var, o, 16);
    float rstd = rsqrtf(var * (1.f / 16.f) + 1e-5f);
    float y = fmaxf(d * rstd * g2[c] + be2[c], 0.f);
    g_Z2F2[(size_t)r * 32 + 16 + c] = y;
    float d3 = y * p3[16 + c];
    for (int o = 8; o; o >>= 1) d3 += __shfl_xor_sync(0xffffffffu, d3, o, 16);
    if (c == 0) g_se3a[r] = d3;
}

// edge MLP (layer 4): Yh = Z2F2[E,32] @ W4[32,16]
__device__ __forceinline__ void dev_mlp4(const float* __restrict__ W4, int rowBase,
                                         float* sh) {
    float* sW = sh;
    int tid = threadIdx.x;
    sW[(tid >> 4) * 16 + (tid & 15)] = W4[tid];
    sW[(16 + (tid >> 4)) * 16 + (tid & 15)] = W4[256 + tid];
    __syncthreads();
    int c = tid & 15;
    int r = rowBase + (tid >> 4);
    float z0 = g_Z2F2[(size_t)r * 32 + c];
    float z1 = g_Z2F2[(size_t)r * 32 + 16 + c];
    float a = 0.f;
#pragma unroll
    for (int k = 0; k < 16; k++) {
        a += __shfl_sync(0xffffffffu, z0, k, 16) * sW[k * 16 + c];
        a += __shfl_sync(0xffffffffu, z1, k, 16) * sW[(16 + k) * 16 + c];
    }
    g_Yh[(size_t)r * 16 + c] = a;
}

// slot-parallel edge multiplier values + column max (sn = sna[+snb])
__device__ __forceinline__ void dev_edge_vals(const float* __restrict__ sna,
                                              const float* __restrict__ snb,
                                              unsigned* __restrict__ cmax, int idx) {
    int e = idx / ELLW;
    int i = idx - e * ELLW;
    int n = g_en[e]; if (n > ELLW) n = ELLW;
    if (i >= n) return;
    int a = g_Ea[e];
    int b = g_Eb[e];
    float sa = sna[a] + (snb ? snb[a] : 0.f);
    float sb = (b >= 0) ? (sna[b] + (snb ? snb[b] : 0.f)) : 0.f;
    float v = g_cC[idx] + g_cA[idx] * sa + g_cB[idx] * sb;
    g_adjEv[idx] = v;
    if (v > 0.f) atomicMax(&cmax[g_ecol[idx]], __float_as_uint(v));
}

// node SpMM rowpair: block handles rows {2*pb, 2*pb+1}; se = sea[+seb]
__device__ __forceinline__ void dev_node_spmm(const float* __restrict__ Y,
                                              const float* __restrict__ bias,
                                              const float* __restrict__ sea,
                                              const float* __restrict__ seb,
                                              float* __restrict__ out,
                                              int ldo, int do_relu,
                                              const float* __restrict__ pgate,
                                              float* __restrict__ gateOut,
                                              int pb, float* sh) {
    int row = pb * 2 + (threadIdx.x >> 7);
    int c = threadIdx.x & 127;
    int n = g_vn[row]; if (n > ELLW) n = ELLW;
    int base = row * ELLW;
    float acc = bias[c];
    for (int i = 0; i < n; i++) {
        int col = g_vcol[base + i];
        float val = g_vval[base + i];
        float mult;
        if (col == row) {
            mult = 1.f;
        } else {
            int cnt = g_scnt[base + i];
            if (cnt > MAXPAR) cnt = MAXPAR;
            mult = 0.f;
            for (int q = 0; q < cnt; q++) {
                int e = g_eid[(base + i) * MAXPAR + q];
                mult += sea[e];
                if (seb) mult += seb[e];
            }
        }
        acc += val * mult * Y[(size_t)col * NH + c];
    }
    if (do_relu) acc = fmaxf(acc, 0.f);
    out[(size_t)row * ldo + c] = acc;
    if (pgate) {
        float dp = acc * pgate[c];
        for (int o = 16; o; o >>= 1) dp += __shfl_xor_sync(0xffffffffu, dp, o);
        int warp = threadIdx.x >> 5;
        if ((threadIdx.x & 31) == 0) sh[warp] = dp;
        __syncthreads();
        if ((threadIdx.x & 127) == 0) {
            int w0 = (threadIdx.x >> 7) * 4;
            gateOut[row] = sh[w0] + sh[w0 + 1] + sh[w0 + 2] + sh[w0 + 3];
        }
    }
}

// ================= kernels =================

// ---- fused dense stage: mlp2 | gemm(X@W1) | gemm(X@Wf1)+LN+sn2a | init ----
__global__ void __launch_bounds__(256, 2)
k_dense1(const float* __restrict__ X, const float* __restrict__ Z,
         const float* __restrict__ W1, const float* __restrict__ Wf1,
         const float* __restrict__ g1, const float* __restrict__ be1,
         const float* __restrict__ W2, const float* __restrict__ Wf2,
         const float* __restrict__ g2, const float* __restrict__ be2,
         const float* __restrict__ p1, const float* __restrict__ p2,
         const float* __restrict__ p3) {
    __shared__ float sh[2048];
    int vb = blockIdx.x;
    if (vb < 256) {
        dev_mlp2(Z, W2, Wf2, g2, be2, p1, p3, vb * 16, sh);
    } else if (vb < 384) {
        dev_gemm_rb<0>(X, W1, g_Y, FV, (vb - 256) * 16, 0, 0, 0, 0, sh);
    } else if (vb < 512) {
        dev_gemm_rb<1>(X, Wf1, 0, FV, (vb - 384) * 16, g1, be1, p2, g_X1F1 + NH, sh);
    } else {
        int t = (vb - 512) * 256 + threadIdx.x;
        for (int i = t; i < N_NODES * ELLW; i += 64 * 256) g_scnt[i] = 0;
        if (t < N_EDGES) {
            g_Ecnt[t] = 0; g_Ea[t] = 0; g_Eb[t] = -1;
            g_Ewa[t] = 0.f; g_Ewb[t] = 0.f;
            g_en[t] = 0;
            g_cmax2[t] = 0u; g_cmax4[t] = 0u;
            if (t < N_NODES) g_vn[t] = 0;
        }
    }
}

// ---- fused dense scan: T + adjV + adjE -> structures ----
#define T4_CNT   (N_NODES * N_EDGES / 4)
#define V4_CNT   (N_NODES * N_NODES / 4)
#define E4_CNT   (N_EDGES * N_EDGES / 4)
#define TOTAL4   (T4_CNT + V4_CNT + E4_CNT)

__device__ __forceinline__ float4 scan_load(const float4* T4, const float4* V4,
                                            const float4* E4, int idx) {
    const float4* p; int li;
    if (idx < T4_CNT)               { p = T4; li = idx; }
    else if (idx < T4_CNT + V4_CNT) { p = V4; li = idx - T4_CNT; }
    else                            { p = E4; li = idx - T4_CNT - V4_CNT; }
    return __ldg(p + li);
}

__device__ __forceinline__ void scan_proc(float4 v, int idx) {
    if (v.x == 0.f && v.y == 0.f && v.z == 0.f && v.w == 0.f) return;
    float vv[4] = {v.x, v.y, v.z, v.w};
    if (idx < T4_CNT) {
        int n = idx >> 10;
        int e0 = (idx & 1023) * 4;
#pragma unroll
        for (int s = 0; s < 4; s++) {
            if (vv[s] != 0.f) {
                int e = e0 + s;
                int slot = atomicAdd(&g_Ecnt[e], 1);
                if (slot == 0) { g_Ea[e] = n; g_Ewa[e] = vv[s]; }
                else           { g_Eb[e] = n; g_Ewb[e] = vv[s]; }
            }
        }
    } else if (idx < T4_CNT + V4_CNT) {
        int i = idx - T4_CNT;
        int r = i >> 9;
        int c0 = (i & 511) * 4;
#pragma unroll
        for (int s = 0; s < 4; s++) {
            if (vv[s] != 0.f) {
                int slot = atomicAdd(&g_vn[r], 1);
                if (slot < ELLW) {
                    g_vcol[r * ELLW + slot] = c0 + s;
                    g_vval[r * ELLW + slot] = vv[s];
                }
            }
        }
    } else {
        int i = idx - T4_CNT - V4_CNT;
        int r = i >> 10;
        int c0 = (i & 1023) * 4;
#pragma unroll
        for (int s = 0; s < 4; s++) {
            if (vv[s] != 0.f) {
                int slot = atomicAdd(&g_en[r], 1);
                if (slot < ELLW) {
                    g_ecol[r * ELLW + slot] = c0 + s;
                    g_eval[r * ELLW + slot] = vv[s];
                }
            }
        }
    }
}

__global__ void k_scan_all(const float4* __restrict__ T4,
                           const float4* __restrict__ V4,
                           const float4* __restrict__ E4) {
    int stride = gridDim.x * blockDim.x;
    int i = blockIdx.x * blockDim.x + threadIdx.x;
    for (; i + 3 * stride < TOTAL4; i += 4 * stride) {
        float4 v0 = scan_load(T4, V4, E4, i);
        float4 v1 = scan_load(T4, V4, E4, i + stride);
        float4 v2 = scan_load(T4, V4, E4, i + 2 * stride);
        float4 v3 = scan_load(T4, V4, E4, i + 3 * stride);
        scan_proc(v0, i);
        scan_proc(v1, i + stride);
        scan_proc(v2, i + 2 * stride);
        scan_proc(v3, i + 3 * stride);
    }
    for (; i < TOTAL4; i += stride) scan_proc(scan_load(T4, V4, E4, i), i);
}

// ---- link edges into adj_v slots + adj_e coef precompute ----
__device__ __forceinline__ void link_one(int r, int c, int e) {
    int n = g_vn[r]; if (n > ELLW) n = ELLW;
    int base = r * ELLW;
    for (int i = 0; i < n; i++) {
        if (g_vcol[base + i] == c) {
            int p = atomicAdd(&g_scnt[base + i], 1);
            if (p < MAXPAR) g_eid[(base + i) * MAXPAR + p] = e;
            return;
        }
    }
}
__global__ void k_link_ecoef() {
    int e = blockIdx.x * blockDim.x + threadIdx.x;
    if (e >= N_EDGES) return;
    int a = g_Ea[e], b = g_Eb[e];
    float wa = g_Ewa[e], wb = g_Ewb[e];
    if (b >= 0 && a != b) { link_one(a, b, e); link_one(b, a, e); }
    int n = g_en[e]; if (n > ELLW) n = ELLW;
    size_t base = (size_t)e * ELLW;
    for (int i = 0; i < n; i++) {
        int f = g_ecol[base + i];
        float ev = g_eval[base + i];
        float cA = 0.f, cB = 0.f, cC = 0.f;
        if (f == e) {
            cC = ev;
        } else {
            int c = g_Ea[f], d = g_Eb[f];
            float wc = g_Ewa[f], wd = g_Ewb[f];
            float ma = 0.f, mb = 0.f;
            if (a == c) ma += wc;
            if (d >= 0 && a == d) ma += wd;
            if (b >= 0) {
                if (b == c) mb += wc;
                if (d >= 0 && b == d) mb += wd;
            }
            cA = ev * wa * ma;
            cB = ev * wb * mb;
        }
        g_cA[base + i] = cA; g_cB[base + i] = cB; g_cC[base + i] = cC;
    }
}

// ---- layer 1 node spmm: X1 (+sn2b direct) ----
__global__ void k_spmm1(const float* __restrict__ b1, const float* __restrict__ p2) {
    __shared__ float sh[8];
    dev_node_spmm(g_Y, b1, g_se1, 0, g_X1F1, 2 * NH, 1, p2, g_sn2b, blockIdx.x, sh);
}

// ---- vals2 | gemm3 merged ----
__global__ void __launch_bounds__(256, 2)
k_vals2_gemm3(const float* __restrict__ W3) {
    __shared__ float sh[1];
    int vb = blockIdx.x;
    if (vb < 640) {
        int idx = vb * 256 + threadIdx.x;
        if (idx < N_EDGES * ELLW) dev_edge_vals(g_sn2a, g_sn2b, g_cmax2, idx);
    } else {
        dev_gemm_rb<0>(g_X1F1, W3, g_tmpN, 2 * NH, (vb - 640) * 16, 0, 0, 0, 0, sh);
    }
}

// ---- edge spmm (generic): out rows, relu, direct gate write ----
__global__ void k_edge_spmm(const float* __restrict__ bias,
                            const unsigned* __restrict__ cmax,
                            float* __restrict__ out, int ldo,
                            const float* __restrict__ p, float* __restrict__ seOut) {
    int t = blockIdx.x * blockDim.x + threadIdx.x;
    int r = t >> 4;
    int c = t & 15;
    if (r >= N_EDGES) return;
    int n = g_en[r]; if (n > ELLW) n = ELLW;
    size_t base = (size_t)r * ELLW;
    float acc = bias[c];
    for (int i = 0; i < n; i++) {
        int f = g_ecol[base + i];
        float w = g_adjEv[base + i] / __uint_as_float(cmax[f]);
        acc += w * g_Yh[(size_t)f * FE + c];
    }
    acc = fmaxf(acc, 0.f);
    out[(size_t)r * ldo + c] = acc;
    float dp = acc * p[c];
    for (int o = 8; o; o >>= 1) dp += __shfl_xor_sync(0xffffffffu, dp, o, 16);
    if (c == 0) seOut[r] = dp;
}

// ---- spmm3 | mlp4 merged ----
__global__ void k_spmm3_mlp4(const float* __restrict__ b3, const float* __restrict__ p4,
                             const float* __restrict__ W4) {
    __shared__ float sh[512];
    int vb = blockIdx.x;
    if (vb < 1024) {
        dev_node_spmm(g_tmpN, b3, g_se3a, g_se3b, g_X3, NH, 1, p4, g_sn4, vb, sh);
    } else {
        dev_mlp4(W4, (vb - 1024) * 16, sh);
    }
}

// ---- vals4 | gemm5 merged ----
__global__ void __launch_bounds__(256, 2)
k_vals4_gemm5(const float* __restrict__ W5) {
    __shared__ float sh[1];
    int vb = blockIdx.x;
    if (vb < 640) {
        int idx = vb * 256 + threadIdx.x;
        if (idx < N_EDGES * ELLW) dev_edge_vals(g_sn4, 0, g_cmax4, idx);
    } else {
        dev_gemm_rb<0>(g_X3, W5, g_tmpN, NH, (vb - 640) * 16, 0, 0, 0, 0, sh);
    }
}

// ---- final node spmm: out (no relu, no gate) ----
__global__ void k_spmm5(const float* __restrict__ b5, float* __restrict__ out) {
    __shared__ float sh[8];
    dev_node_spmm(g_tmpN, b5, g_se5, 0, out, NC, 0, 0, 0, blockIdx.x, sh);
}

// ================= host =================
extern "C" void kernel_launch(void* const* d_in, const int* in_sizes, int n_in,
                              void* d_out, int out_size) {
    const float* X    = (const float*)d_in[0];
    const float* Z    = (const float*)d_in[1];
    const float* adjE = (const float*)d_in[2];
    const float* adjV = (const float*)d_in[3];
    const float* T    = (const float*)d_in[4];
    const float* W1  = (const float*)d_in[5];
    const float* p1  = (const float*)d_in[6];
    const float* b1  = (const float*)d_in[7];
    const float* Wf1 = (const float*)d_in[8];
    const float* g1  = (const float*)d_in[9];
    const float* be1 = (const float*)d_in[10];
    const float* W2  = (const float*)d_in[11];
    const float* p2  = (const float*)d_in[12];
    const float* b2  = (const float*)d_in[13];
    const float* Wf2 = (const float*)d_in[14];
    const float* g2  = (const float*)d_in[15];
    const float* be2 = (const float*)d_in[16];
    const float* W3  = (const float*)d_in[17];
    const float* p3  = (const float*)d_in[18];
    const float* b3  = (const float*)d_in[19];
    const float* W4  = (const float*)d_in[20];
    const float* p4  = (const float*)d_in[21];
    const float* b4  = (const float*)d_in[22];
    const float* W5  = (const float*)d_in[23];
    const float* p5  = (const float*)d_in[24];
    const float* b5  = (const float*)d_in[25];
    float* out = (float*)d_out;

    float *pse3b, *pse5, *pZ2F2, *pZ4;
    unsigned *pcm2, *pcm4;
    cudaGetSymbolAddress((void**)&pse3b, g_se3b);
    cudaGetSymbolAddress((void**)&pse5, g_se5);
    cudaGetSymbolAddress((void**)&pZ2F2, g_Z2F2);
    cudaGetSymbolAddress((void**)&pZ4, g_Z4);
    cudaGetSymbolAddress((void**)&pcm2, g_cmax2);
    cudaGetSymbolAddress((void**)&pcm4, g_cmax4);

    // 1: fused dense stage (mlp2 | gemm1 | gemm1f+LN | init)
    k_dense1<<<576, 256>>>(X, Z, W1, Wf1, g1, be1, W2, Wf2, g2, be2, p1, p2, p3);
    // 2: structure scan
    k_scan_all<<<2048, 256>>>((const float4*)T, (const float4*)adjV, (const float4*)adjE);
    // 3: link + coefs
    k_link_ecoef<<<16, 256>>>();
    // 4: layer-1 node spmm (X1, sn2b)
    k_spmm1<<<1024, 256>>>(b1, p2);
    // 5: vals2 | gemm3
    k_vals2_gemm3<<<768, 256>>>(W3);
    // 6: layer-2 edge spmm (Z2, se3b)
    k_edge_spmm<<<256, 256>>>(b2, pcm2, pZ2F2, 2 * FE, p3, pse3b);
    // 7: spmm3 | mlp4 (X3, sn4, Yh)
    k_spmm3_mlp4<<<1280, 256>>>(b3, p4, W4);
    // 8: vals4 | gemm5
    k_vals4_gemm5<<<768, 256>>>(W5);
    // 9: layer-4 edge spmm (Z4, se5)
    k_edge_spmm<<<256, 256>>>(b4, pcm4, pZ4, FE, p5, pse5);
    // 10: final node spmm -> out
    k_spmm5<<<1024, 256>>>(b5, out);
}

// round 15
// speedup vs baseline: 1.5476x; 1.5476x over previous
#include <cuda_runtime.h>

#define N_NODES 2048
#define N_EDGES 4096
#define FV 64
#define FE 16
#define NH 128
#define NC 128

#define ELLW 40
#define MAXPAR 4

// ---------------- scratch (device globals; no allocation) ----------------
__device__ float g_Y[N_NODES * NH];
__device__ float g_tmpN[N_NODES * NH];
__device__ float g_X1F1[N_NODES * 2 * NH];
__device__ float g_X3[N_NODES * NH];
__device__ float g_Yh[N_EDGES * FE];
__device__ float g_Z2F2[N_EDGES * 2 * FE];
__device__ float g_Z4[N_EDGES * FE];

// gates (se1/se5 written fully; se3/sn2/sn4 accumulated -> zeroed in init)
__device__ float g_se1[N_EDGES];
__device__ float g_se3[N_EDGES];
__device__ float g_se5[N_EDGES];
__device__ float g_sn2[N_NODES];
__device__ float g_sn4[N_NODES];

// adj_v ELL (unordered)
__device__ int   g_vn[N_NODES];
__device__ int   g_vcol[N_NODES * ELLW];
__device__ float g_vval[N_NODES * ELLW];
__device__ int   g_scnt[N_NODES * ELLW];
__device__ int   g_eid[N_NODES * ELLW * MAXPAR];

// adj_e ELL (unordered)
__device__ int      g_en[N_EDGES];
__device__ int      g_ecol[N_EDGES * ELLW];
__device__ float    g_eval[N_EDGES * ELLW];
__device__ float    g_cA[N_EDGES * ELLW];
__device__ float    g_cB[N_EDGES * ELLW];
__device__ float    g_cC[N_EDGES * ELLW];
__device__ float    g_adjEv[N_EDGES * ELLW];
__device__ unsigned g_cmax2[N_EDGES];
__device__ unsigned g_cmax4[N_EDGES];

// edge endpoints from T
__device__ int   g_Ea[N_EDGES];
__device__ int   g_Eb[N_EDGES];
__device__ float g_Ewa[N_EDGES];
__device__ float g_Ewb[N_EDGES];
__device__ int   g_Ecnt[N_EDGES];

// ---------------- init: zero all accumulated state ----------------
__global__ void k_init() {
    int stride = gridDim.x * blockDim.x;
    for (int i = blockIdx.x * blockDim.x + threadIdx.x; i < N_NODES * ELLW; i += stride)
        g_scnt[i] = 0;
    for (int i = blockIdx.x * blockDim.x + threadIdx.x; i < N_EDGES; i += stride) {
        g_Ecnt[i] = 0; g_Ea[i] = 0; g_Eb[i] = -1;
        g_Ewa[i] = 0.f; g_Ewb[i] = 0.f;
        g_en[i] = 0;
        g_se3[i] = 0.f;
        g_cmax2[i] = 0u; g_cmax4[i] = 0u;
        if (i < N_NODES) { g_vn[i] = 0; g_sn2[i] = 0.f; g_sn4[i] = 0.f; }
    }
}

// ---------------- fused dense scan: T + adjV + adjE -> structures ----------------
#define T4_CNT   (N_NODES * N_EDGES / 4)
#define V4_CNT   (N_NODES * N_NODES / 4)
#define E4_CNT   (N_EDGES * N_EDGES / 4)
#define TOTAL4   (T4_CNT + V4_CNT + E4_CNT)

__device__ __forceinline__ float4 scan_load(const float4* T4, const float4* V4,
                                            const float4* E4, int idx) {
    const float4* p; int li;
    if (idx < T4_CNT)               { p = T4; li = idx; }
    else if (idx < T4_CNT + V4_CNT) { p = V4; li = idx - T4_CNT; }
    else                            { p = E4; li = idx - T4_CNT - V4_CNT; }
    return __ldg(p + li);
}

__device__ __forceinline__ void scan_proc(float4 v, int idx) {
    if (v.x == 0.f && v.y == 0.f && v.z == 0.f && v.w == 0.f) return;
    float vv[4] = {v.x, v.y, v.z, v.w};
    if (idx < T4_CNT) {
        int n = idx >> 10;
        int e0 = (idx & 1023) * 4;
#pragma unroll
        for (int s = 0; s < 4; s++) {
            if (vv[s] != 0.f) {
                int e = e0 + s;
                int slot = atomicAdd(&g_Ecnt[e], 1);
                if (slot == 0) { g_Ea[e] = n; g_Ewa[e] = vv[s]; }
                else           { g_Eb[e] = n; g_Ewb[e] = vv[s]; }
            }
        }
    } else if (idx < T4_CNT + V4_CNT) {
        int i = idx - T4_CNT;
        int r = i >> 9;
        int c0 = (i & 511) * 4;
#pragma unroll
        for (int s = 0; s < 4; s++) {
            if (vv[s] != 0.f) {
                int slot = atomicAdd(&g_vn[r], 1);
                if (slot < ELLW) {
                    g_vcol[r * ELLW + slot] = c0 + s;
                    g_vval[r * ELLW + slot] = vv[s];
                }
            }
        }
    } else {
        int i = idx - T4_CNT - V4_CNT;
        int r = i >> 10;
        int c0 = (i & 1023) * 4;
#pragma unroll
        for (int s = 0; s < 4; s++) {
            if (vv[s] != 0.f) {
                int slot = atomicAdd(&g_en[r], 1);
                if (slot < ELLW) {
                    g_ecol[r * ELLW + slot] = c0 + s;
                    g_eval[r * ELLW + slot] = vv[s];
                }
            }
        }
    }
}

__global__ void k_scan_all(const float4* __restrict__ T4,
                           const float4* __restrict__ V4,
                           const float4* __restrict__ E4) {
    int stride = gridDim.x * blockDim.x;
    int i = blockIdx.x * blockDim.x + threadIdx.x;
    for (; i + 3 * stride < TOTAL4; i += 4 * stride) {
        float4 v0 = scan_load(T4, V4, E4, i);
        float4 v1 = scan_load(T4, V4, E4, i + stride);
        float4 v2 = scan_load(T4, V4, E4, i + 2 * stride);
        float4 v3 = scan_load(T4, V4, E4, i + 3 * stride);
        scan_proc(v0, i);
        scan_proc(v1, i + stride);
        scan_proc(v2, i + 2 * stride);
        scan_proc(v3, i + 3 * stride);
    }
    for (; i < TOTAL4; i += stride) scan_proc(scan_load(T4, V4, E4, i), i);
}

// ---------------- link edges into adj_v slots + adj_e coef precompute ----------------
__device__ __forceinline__ void link_one(int r, int c, int e) {
    int n = g_vn[r]; if (n > ELLW) n = ELLW;
    int base = r * ELLW;
    for (int i = 0; i < n; i++) {
        if (g_vcol[base + i] == c) {
            int p = atomicAdd(&g_scnt[base + i], 1);
            if (p < MAXPAR) g_eid[(base + i) * MAXPAR + p] = e;
            return;
        }
    }
}
__global__ void k_link_ecoef() {
    int e = blockIdx.x * blockDim.x + threadIdx.x;
    if (e >= N_EDGES) return;
    int a = g_Ea[e], b = g_Eb[e];
    float wa = g_Ewa[e], wb = g_Ewb[e];
    if (b >= 0 && a != b) { link_one(a, b, e); link_one(b, a, e); }
    int n = g_en[e]; if (n > ELLW) n = ELLW;
    size_t base = (size_t)e * ELLW;
    for (int i = 0; i < n; i++) {
        int f = g_ecol[base + i];
        float ev = g_eval[base + i];
        float cA = 0.f, cB = 0.f, cC = 0.f;
        if (f == e) {
            cC = ev;
        } else {
            int c = g_Ea[f], d = g_Eb[f];
            float wc = g_Ewa[f], wd = g_Ewb[f];
            float ma = 0.f, mb = 0.f;
            if (a == c) ma += wc;
            if (d >= 0 && a == d) ma += wd;
            if (b >= 0) {
                if (b == c) mb += wc;
                if (d >= 0 && b == d) mb += wd;
            }
            cA = ev * wa * ma;
            cB = ev * wb * mb;
        }
        g_cA[base + i] = cA; g_cB[base + i] = cB; g_cC[base + i] = cC;
    }
}

// ---------------- slot-parallel edge multiplier values + column max ----------------
__global__ void k_edge_vals(const float* __restrict__ sn, unsigned* __restrict__ cmax) {
    int idx = blockIdx.x * blockDim.x + threadIdx.x;
    if (idx >= N_EDGES * ELLW) return;
    int e = idx / ELLW;
    int i = idx - e * ELLW;
    int n = g_en[e]; if (n > ELLW) n = ELLW;
    if (i >= n) return;
    float sa = sn[g_Ea[e]];
    int b = g_Eb[e];
    float sb = (b >= 0) ? sn[b] : 0.f;
    float v = g_cC[idx] + g_cA[idx] * sa + g_cB[idx] * sb;
    g_adjEv[idx] = v;
    if (v > 0.f) atomicMax(&cmax[g_ecol[idx]], __float_as_uint(v));
}

// ---------------- register-B GEMM: C[M,128] = A[M,K] @ B[K,128] ----------------
__global__ void __launch_bounds__(256, 2)
k_gemmRB(const float* __restrict__ A,
         const float* __restrict__ B1, const float* __restrict__ B2,
         float* __restrict__ C1, float* __restrict__ C2, int K) {
    const float* __restrict__ B = blockIdx.y ? B2 : B1;
    float* __restrict__ C = blockIdx.y ? C2 : C1;
    int col = threadIdx.x & 127;
    int half = threadIdx.x >> 7;
    int rowBase = blockIdx.x * 16;
    float acc[8];
#pragma unroll
    for (int r = 0; r < 8; r++) acc[r] = 0.f;
    for (int kc = 0; kc < K; kc += 64) {
        float breg[64];
#pragma unroll
        for (int k = 0; k < 64; k++) breg[k] = B[(size_t)(kc + k) * 128 + col];
#pragma unroll
        for (int r = 0; r < 8; r++) {
            int row = rowBase + r * 2 + half;
            const float4* a4 = (const float4*)(A + (size_t)row * K + kc);
            float s = 0.f;
#pragma unroll
            for (int k4 = 0; k4 < 16; k4++) {
                float4 a = a4[k4];
                s += a.x * breg[4 * k4 + 0];
                s += a.y * breg[4 * k4 + 1];
                s += a.z * breg[4 * k4 + 2];
                s += a.w * breg[4 * k4 + 3];
            }
            acc[r] += s;
        }
    }
#pragma unroll
    for (int r = 0; r < 8; r++)
        C[(size_t)(rowBase + r * 2 + half) * 128 + col] = acc[r];
}

// ---------------- layernorm + relu -> F1, + partial sn2 (cols 128..255 of p2) ------
__global__ void k_ln_relu(const float* __restrict__ in, const float* __restrict__ g,
                          const float* __restrict__ b, const float* __restrict__ p2,
                          float* __restrict__ out) {
    int w = (blockIdx.x * blockDim.x + threadIdx.x) >> 5;   // row
    int lane = threadIdx.x & 31;
    if (w >= N_NODES) return;
    float v[4];
    float sum = 0.f;
#pragma unroll
    for (int i = 0; i < 4; i++) {
        v[i] = in[(size_t)w * 128 + lane + 32 * i];
        sum += v[i];
    }
    for (int o = 16; o; o >>= 1) sum += __shfl_xor_sync(0xffffffffu, sum, o);
    float mean = sum * (1.f / 128.f);
    float var = 0.f;
#pragma unroll
    for (int i = 0; i < 4; i++) { float d = v[i] - mean; var += d * d; }
    for (int o = 16; o; o >>= 1) var += __shfl_xor_sync(0xffffffffu, var, o);
    float rstd = rsqrtf(var * (1.f / 128.f) + 1e-5f);
    float dotp = 0.f;
#pragma unroll
    for (int i = 0; i < 4; i++) {
        int idx = lane + 32 * i;
        float y = (v[i] - mean) * rstd * g[idx] + b[idx];
        y = fmaxf(y, 0.f);
        out[(size_t)w * 256 + idx] = y;
        dotp += y * p2[128 + idx];
    }
    for (int o = 16; o; o >>= 1) dotp += __shfl_xor_sync(0xffffffffu, dotp, o);
    if (lane == 0) atomicAdd(&g_sn2[w], dotp);
}

// ---------------- fused edge MLP (layer 2) + se1 + partial se3 ----------------
__global__ void k_edge_mlp2(const float* __restrict__ Z, const float* __restrict__ W2,
                            const float* __restrict__ Wf2, const float* __restrict__ g2,
                            const float* __restrict__ be2, const float* __restrict__ p1,
                            const float* __restrict__ p3,
                            float* __restrict__ Yh, float* __restrict__ Z2F2) {
    __shared__ float sW[256], sF[256];
    int tid = threadIdx.x;
    sW[tid] = W2[tid];
    sF[tid] = Wf2[tid];
    __syncthreads();
    int c = tid & 15;
    int r = blockIdx.x * 16 + (tid >> 4);
    float zc = Z[(size_t)r * 16 + c];
    float a1 = 0.f, a2 = 0.f;
#pragma unroll
    for (int k = 0; k < 16; k++) {
        float zk = __shfl_sync(0xffffffffu, zc, k, 16);
        a1 += fmaxf(zk, 0.f) * sW[k * 16 + c];
        a2 += zk * sF[k * 16 + c];
    }
    Yh[(size_t)r * 16 + c] = a1;
    float d1 = zc * p1[c];
    for (int o = 8; o; o >>= 1) d1 += __shfl_xor_sync(0xffffffffu, d1, o, 16);
    if (c == 0) g_se1[r] = d1;
    float sum = a2;
    for (int o = 8; o; o >>= 1) sum += __shfl_xor_sync(0xffffffffu, sum, o, 16);
    float mean = sum * (1.f / 16.f);
    float d = a2 - mean;
    float var = d * d;
    for (int o = 8; o; o >>= 1) var += __shfl_xor_sync(0xffffffffu, var, o, 16);
    float rstd = rsqrtf(var * (1.f / 16.f) + 1e-5f);
    float y = fmaxf(d * rstd * g2[c] + be2[c], 0.f);
    Z2F2[(size_t)r * 32 + 16 + c] = y;
    float d3 = y * p3[16 + c];
    for (int o = 8; o; o >>= 1) d3 += __shfl_xor_sync(0xffffffffu, d3, o, 16);
    if (c == 0) atomicAdd(&g_se3[r], d3);
}

// ---------------- edge MLP (layer 4): Yh = Z2F2[E,32] @ W4[32,16] ----------------
__global__ void k_edge_mlp4(const float* __restrict__ A, const float* __restrict__ W4,
                            float* __restrict__ Yh) {
    __shared__ float sW[512];
    int tid = threadIdx.x;
    sW[(tid >> 4) * 16 + (tid & 15)] = W4[tid];
    sW[(16 + (tid >> 4)) * 16 + (tid & 15)] = W4[256 + tid];
    __syncthreads();
    int c = tid & 15;
    int r = blockIdx.x * 16 + (tid >> 4);
    float z0 = A[(size_t)r * 32 + c];
    float z1 = A[(size_t)r * 32 + 16 + c];
    float a = 0.f;
#pragma unroll
    for (int k = 0; k < 16; k++) {
        a += __shfl_sync(0xffffffffu, z0, k, 16) * sW[k * 16 + c];
        a += __shfl_sync(0xffffffffu, z1, k, 16) * sW[(16 + k) * 16 + c];
    }
    Yh[(size_t)r * 16 + c] = a;
}

// ---------------- node SpMM: two-phase (smem-staged structure) ----------------
// block = 256 = 2 rows x 128 cols. Phase 1: warp 0 of each half resolves nnz
// (col, val*mult) in parallel across lanes. Phase 2: independent Y gathers.
__global__ void k_node_spmm(const float* __restrict__ Y, const float* __restrict__ bias,
                            const float* __restrict__ se, float* __restrict__ out,
                            int ldo, int do_relu,
                            const float* __restrict__ pgate, float* __restrict__ snOut) {
    __shared__ float s_mv[2][ELLW];
    __shared__ int   s_col[2][ELLW];
    int tid = threadIdx.x;
    int half = tid >> 7;
    int row = blockIdx.x * 2 + half;
    int n = g_vn[row]; if (n > ELLW) n = ELLW;
    int base = row * ELLW;
    if (((tid >> 5) & 3) == 0) {
        int lane = tid & 31;
        for (int i = lane; i < n; i += 32) {
            int col = g_vcol[base + i];
            float val = g_vval[base + i];
            float mult;
            if (col == row) {
                mult = 1.f;
            } else {
                int cnt = g_scnt[base + i];
                if (cnt > MAXPAR) cnt = MAXPAR;
                mult = 0.f;
#pragma unroll
                for (int q = 0; q < MAXPAR; q++)
                    if (q < cnt) mult += se[g_eid[(base + i) * MAXPAR + q]];
            }
            s_col[half][i] = col;
            s_mv[half][i] = val * mult;
        }
    }
    __syncthreads();
    int c = tid & 127;
    float acc = bias[c];
    for (int i = 0; i < n; i++)
        acc += s_mv[half][i] * Y[(size_t)s_col[half][i] * NH + c];
    if (do_relu) acc = fmaxf(acc, 0.f);
    out[(size_t)row * ldo + c] = acc;
    if (pgate) {
        float dp = acc * pgate[c];
        for (int o = 16; o; o >>= 1) dp += __shfl_xor_sync(0xffffffffu, dp, o);
        if ((tid & 31) == 0) atomicAdd(&snOut[row], dp);
    }
}

// ---------------- edge SpMM: two-phase (smem-staged weights) ----------------
// block = 256 = 16 rows x 16 cols. Phase 1: each thread resolves slots
// (t&15, +16, ...) for its row: f and adjEv/cmax[f]. Phase 2: Yh gathers.
// gmode: 0 none; 1 atomicAdd partial (se3); 2 direct write (se5)
__global__ void k_edge_spmm(const float* __restrict__ Yh, const float* __restrict__ bias,
                            const unsigned* __restrict__ cmax, float* __restrict__ out,
                            int ldo, const float* __restrict__ p, float* __restrict__ seOut,
                            int gmode) {
    __shared__ float s_w[16][ELLW];
    __shared__ int   s_f[16][ELLW];
    int tid = threadIdx.x;
    int rl = tid >> 4;          // local row 0..15
    int c = tid & 15;
    int r = blockIdx.x * 16 + rl;
    int n = g_en[r]; if (n > ELLW) n = ELLW;
    size_t base = (size_t)r * ELLW;
    for (int i = c; i < n; i += 16) {
        int f = g_ecol[base + i];
        s_f[rl][i] = f;
        s_w[rl][i] = g_adjEv[base + i] / __uint_as_float(cmax[f]);
    }
    __syncthreads();
    float acc = bias[c];
    for (int i = 0; i < n; i++)
        acc += s_w[rl][i] * Yh[(size_t)s_f[rl][i] * FE + c];
    acc = fmaxf(acc, 0.f);
    out[(size_t)r * ldo + c] = acc;
    if (gmode) {
        float dp = acc * p[c];
        for (int o = 8; o; o >>= 1) dp += __shfl_xor_sync(0xffffffffu, dp, o, 16);
        if (c == 0) {
            if (gmode == 1) atomicAdd(&seOut[r], dp);
            else            seOut[r] = dp;
        }
    }
}

// ---------------- host ----------------
extern "C" void kernel_launch(void* const* d_in, const int* in_sizes, int n_in,
                              void* d_out, int out_size) {
    const float* X    = (const float*)d_in[0];
    const float* Z    = (const float*)d_in[1];
    const float* adjE = (const float*)d_in[2];
    const float* adjV = (const float*)d_in[3];
    const float* T    = (const float*)d_in[4];
    const float* W1  = (const float*)d_in[5];
    const float* p1  = (const float*)d_in[6];
    const float* b1  = (const float*)d_in[7];
    const float* Wf1 = (const float*)d_in[8];
    const float* g1  = (const float*)d_in[9];
    const float* be1 = (const float*)d_in[10];
    const float* W2  = (const float*)d_in[11];
    const float* p2  = (const float*)d_in[12];
    const float* b2  = (const float*)d_in[13];
    const float* Wf2 = (const float*)d_in[14];
    const float* g2  = (const float*)d_in[15];
    const float* be2 = (const float*)d_in[16];
    const float* W3  = (const float*)d_in[17];
    const float* p3  = (const float*)d_in[18];
    const float* b3  = (const float*)d_in[19];
    const float* W4  = (const float*)d_in[20];
    const float* p4  = (const float*)d_in[21];
    const float* b4  = (const float*)d_in[22];
    const float* W5  = (const float*)d_in[23];
    const float* p5  = (const float*)d_in[24];
    const float* b5  = (const float*)d_in[25];
    float* out = (float*)d_out;

    float *pY, *ptmpN, *pX1F1, *pX3, *pYh, *pZ2F2, *pZ4;
    float *pse1, *pse3, *pse5, *psn2, *psn4;
    unsigned *pcm2, *pcm4;
    cudaGetSymbolAddress((void**)&pY, g_Y);
    cudaGetSymbolAddress((void**)&ptmpN, g_tmpN);
    cudaGetSymbolAddress((void**)&pX1F1, g_X1F1);
    cudaGetSymbolAddress((void**)&pX3, g_X3);
    cudaGetSymbolAddress((void**)&pYh, g_Yh);
    cudaGetSymbolAddress((void**)&pZ2F2, g_Z2F2);
    cudaGetSymbolAddress((void**)&pZ4, g_Z4);
    cudaGetSymbolAddress((void**)&pse1, g_se1);
    cudaGetSymbolAddress((void**)&pse3, g_se3);
    cudaGetSymbolAddress((void**)&pse5, g_se5);
    cudaGetSymbolAddress((void**)&psn2, g_sn2);
    cudaGetSymbolAddress((void**)&psn4, g_sn4);
    cudaGetSymbolAddress((void**)&pcm2, g_cmax2);
    cudaGetSymbolAddress((void**)&pcm4, g_cmax4);

    // ---- structure + scan-independent work first ----
    k_init<<<348, 256>>>();
    k_edge_mlp2<<<256, 256>>>(Z, W2, Wf2, g2, be2, p1, p3, pYh, pZ2F2); // Yh, F2, se1, se3+
    k_gemmRB<<<dim3(128, 2), 256>>>(X, W1, Wf1, pY, ptmpN, FV);          // X@W1, X@Wf1
    k_ln_relu<<<256, 256>>>(ptmpN, g1, be1, p2, pX1F1 + NH);             // F1, sn2+
    k_scan_all<<<2048, 256>>>((const float4*)T, (const float4*)adjV, (const float4*)adjE);
    k_link_ecoef<<<16, 256>>>();

    // ---- layer 1: X1 (+sn2 partial) ----
    k_node_spmm<<<1024, 256>>>(pY, b1, pse1, pX1F1, 2 * NH, 1, p2, psn2);

    // ---- layer 2: edge vals + Z2 (+se3 partial) ----
    k_edge_vals<<<640, 256>>>(psn2, pcm2);
    k_edge_spmm<<<256, 256>>>(pYh, b2, pcm2, pZ2F2, 2 * FE, p3, pse3, 1);

    // ---- layer 3: gemm + X3 (+sn4 partial) ----
    k_gemmRB<<<dim3(128, 1), 256>>>(pX1F1, W3, W3, ptmpN, ptmpN, 2 * NH);
    k_node_spmm<<<1024, 256>>>(ptmpN, b3, pse3, pX3, NH, 1, p4, psn4);

    // ---- layer 4: mlp + vals + Z4 (+se5 direct) ----
    k_edge_mlp4<<<256, 256>>>(pZ2F2, W4, pYh);
    k_edge_vals<<<640, 256>>>(psn4, pcm4);
    k_edge_spmm<<<256, 256>>>(pYh, b4, pcm4, pZ4, FE, p5, pse5, 2);

    // ---- layer 5: gemm + out (no relu, no gate) ----
    k_gemmRB<<<dim3(128, 1), 256>>>(pX3, W5, W5, ptmpN, ptmpN, NH);
    k_node_spmm<<<1024, 256>>>(ptmpN, b5, pse5, out, NC, 0, (const float*)0, (float*)0);
}

// round 16
// speedup vs baseline: 1.9968x; 1.2902x over previous
#include <cuda_runtime.h>

#define N_NODES 2048
#define N_EDGES 4096
#define FV 64
#define FE 16
#define NH 128
#define NC 128

#define ELLW 40
#define MAXPAR 4

// ---------------- scratch (device globals; no allocation) ----------------
__device__ float g_Y[N_NODES * NH];
__device__ float g_tmpN[N_NODES * NH];
__device__ float g_X1F1[N_NODES * 2 * NH];
__device__ float g_X3[N_NODES * NH];
__device__ float g_Yh[N_EDGES * FE];
__device__ float g_Z2F2[N_EDGES * 2 * FE];
__device__ float g_Z4[N_EDGES * FE];

// gates (se1/se5 written fully; se3/sn2/sn4 accumulated -> zeroed in init)
__device__ float g_se1[N_EDGES];
__device__ float g_se3[N_EDGES];
__device__ float g_se5[N_EDGES];
__device__ float g_sn2[N_NODES];
__device__ float g_sn4[N_NODES];

// adj_v ELL (unordered)
__device__ int   g_vn[N_NODES];
__device__ int   g_vcol[N_NODES * ELLW];
__device__ float g_vval[N_NODES * ELLW];
__device__ int   g_scnt[N_NODES * ELLW];
__device__ int   g_eid[N_NODES * ELLW * MAXPAR];

// adj_e ELL (unordered)
__device__ int      g_en[N_EDGES];
__device__ int      g_ecol[N_EDGES * ELLW];
__device__ float    g_eval[N_EDGES * ELLW];
__device__ float    g_cA[N_EDGES * ELLW];
__device__ float    g_cB[N_EDGES * ELLW];
__device__ float    g_cC[N_EDGES * ELLW];
__device__ float    g_adjEv[N_EDGES * ELLW];
__device__ unsigned g_cmax2[N_EDGES];
__device__ unsigned g_cmax4[N_EDGES];

// edge endpoints from T
__device__ int   g_Ea[N_EDGES];
__device__ int   g_Eb[N_EDGES];
__device__ float g_Ewa[N_EDGES];
__device__ float g_Ewb[N_EDGES];
__device__ int   g_Ecnt[N_EDGES];

// ---------------- init: zero all accumulated state ----------------
__global__ void k_init() {
    int stride = gridDim.x * blockDim.x;
    for (int i = blockIdx.x * blockDim.x + threadIdx.x; i < N_NODES * ELLW; i += stride)
        g_scnt[i] = 0;
    for (int i = blockIdx.x * blockDim.x + threadIdx.x; i < N_EDGES; i += stride) {
        g_Ecnt[i] = 0; g_Ea[i] = 0; g_Eb[i] = -1;
        g_Ewa[i] = 0.f; g_Ewb[i] = 0.f;
        g_en[i] = 0;
        g_se3[i] = 0.f;
        g_cmax2[i] = 0u; g_cmax4[i] = 0u;
        if (i < N_NODES) { g_vn[i] = 0; g_sn2[i] = 0.f; g_sn4[i] = 0.f; }
    }
}

// ---------------- fused dense scan: T + adjV + adjE -> structures ----------------
#define T4_CNT   (N_NODES * N_EDGES / 4)
#define V4_CNT   (N_NODES * N_NODES / 4)
#define E4_CNT   (N_EDGES * N_EDGES / 4)
#define TOTAL4   (T4_CNT + V4_CNT + E4_CNT)

__device__ __forceinline__ float4 scan_load(const float4* T4, const float4* V4,
                                            const float4* E4, int idx) {
    const float4* p; int li;
    if (idx < T4_CNT)               { p = T4; li = idx; }
    else if (idx < T4_CNT + V4_CNT) { p = V4; li = idx - T4_CNT; }
    else                            { p = E4; li = idx - T4_CNT - V4_CNT; }
    return __ldg(p + li);
}

__device__ __forceinline__ void scan_proc(float4 v, int idx) {
    if (v.x == 0.f && v.y == 0.f && v.z == 0.f && v.w == 0.f) return;
    float vv[4] = {v.x, v.y, v.z, v.w};
    if (idx < T4_CNT) {
        int n = idx >> 10;
        int e0 = (idx & 1023) * 4;
#pragma unroll
        for (int s = 0; s < 4; s++) {
            if (vv[s] != 0.f) {
                int e = e0 + s;
                int slot = atomicAdd(&g_Ecnt[e], 1);
                if (slot == 0) { g_Ea[e] = n; g_Ewa[e] = vv[s]; }
                else           { g_Eb[e] = n; g_Ewb[e] = vv[s]; }
            }
        }
    } else if (idx < T4_CNT + V4_CNT) {
        int i = idx - T4_CNT;
        int r = i >> 9;
        int c0 = (i & 511) * 4;
#pragma unroll
        for (int s = 0; s < 4; s++) {
            if (vv[s] != 0.f) {
                int slot = atomicAdd(&g_vn[r], 1);
                if (slot < ELLW) {
                    g_vcol[r * ELLW + slot] = c0 + s;
                    g_vval[r * ELLW + slot] = vv[s];
                }
            }
        }
    } else {
        int i = idx - T4_CNT - V4_CNT;
        int r = i >> 10;
        int c0 = (i & 1023) * 4;
#pragma unroll
        for (int s = 0; s < 4; s++) {
            if (vv[s] != 0.f) {
                int slot = atomicAdd(&g_en[r], 1);
                if (slot < ELLW) {
                    g_ecol[r * ELLW + slot] = c0 + s;
                    g_eval[r * ELLW + slot] = vv[s];
                }
            }
        }
    }
}

__global__ void k_scan_all(const float4* __restrict__ T4,
                           const float4* __restrict__ V4,
                           const float4* __restrict__ E4) {
    int stride = gridDim.x * blockDim.x;
    int i = blockIdx.x * blockDim.x + threadIdx.x;
    for (; i + 3 * stride < TOTAL4; i += 4 * stride) {
        float4 v0 = scan_load(T4, V4, E4, i);
        float4 v1 = scan_load(T4, V4, E4, i + stride);
        float4 v2 = scan_load(T4, V4, E4, i + 2 * stride);
        float4 v3 = scan_load(T4, V4, E4, i + 3 * stride);
        scan_proc(v0, i);
        scan_proc(v1, i + stride);
        scan_proc(v2, i + 2 * stride);
        scan_proc(v3, i + 3 * stride);
    }
    for (; i < TOTAL4; i += stride) scan_proc(scan_load(T4, V4, E4, i), i);
}

// ---------------- link edges into adj_v slots + adj_e coef precompute ----------------
__device__ __forceinline__ void link_one(int r, int c, int e) {
    int n = g_vn[r]; if (n > ELLW) n = ELLW;
    int base = r * ELLW;
    for (int i = 0; i < n; i++) {
        if (g_vcol[base + i] == c) {
            int p = atomicAdd(&g_scnt[base + i], 1);
            if (p < MAXPAR) g_eid[(base + i) * MAXPAR + p] = e;
            return;
        }
    }
}
__global__ void k_link_ecoef() {
    int e = blockIdx.x * blockDim.x + threadIdx.x;
    if (e >= N_EDGES) return;
    int a = g_Ea[e], b = g_Eb[e];
    float wa = g_Ewa[e], wb = g_Ewb[e];
    if (b >= 0 && a != b) { link_one(a, b, e); link_one(b, a, e); }
    int n = g_en[e]; if (n > ELLW) n = ELLW;
    size_t base = (size_t)e * ELLW;
    for (int i = 0; i < n; i++) {
        int f = g_ecol[base + i];
        float ev = g_eval[base + i];
        float cA = 0.f, cB = 0.f, cC = 0.f;
        if (f == e) {
            cC = ev;
        } else {
            int c = g_Ea[f], d = g_Eb[f];
            float wc = g_Ewa[f], wd = g_Ewb[f];
            float ma = 0.f, mb = 0.f;
            if (a == c) ma += wc;
            if (d >= 0 && a == d) ma += wd;
            if (b >= 0) {
                if (b == c) mb += wc;
                if (d >= 0 && b == d) mb += wd;
            }
            cA = ev * wa * ma;
            cB = ev * wb * mb;
        }
        g_cA[base + i] = cA; g_cB[base + i] = cB; g_cC[base + i] = cC;
    }
}

// ---------------- slot-parallel edge multiplier values + column max ----------------
__global__ void k_edge_vals(const float* __restrict__ sn, unsigned* __restrict__ cmax) {
    int idx = blockIdx.x * blockDim.x + threadIdx.x;
    if (idx >= N_EDGES * ELLW) return;
    int e = idx / ELLW;
    int i = idx - e * ELLW;
    int n = g_en[e]; if (n > ELLW) n = ELLW;
    if (i >= n) return;
    float sa = sn[g_Ea[e]];
    int b = g_Eb[e];
    float sb = (b >= 0) ? sn[b] : 0.f;
    float v = g_cC[idx] + g_cA[idx] * sa + g_cB[idx] * sb;
    g_adjEv[idx] = v;
    if (v > 0.f) atomicMax(&cmax[g_ecol[idx]], __float_as_uint(v));
}

// ---------------- register-B GEMM: C[M,128] = A[M,K] @ B[K,128] ----------------
__global__ void __launch_bounds__(256, 2)
k_gemmRB(const float* __restrict__ A,
         const float* __restrict__ B1, const float* __restrict__ B2,
         float* __restrict__ C1, float* __restrict__ C2, int K) {
    const float* __restrict__ B = blockIdx.y ? B2 : B1;
    float* __restrict__ C = blockIdx.y ? C2 : C1;
    int col = threadIdx.x & 127;
    int half = threadIdx.x >> 7;
    int rowBase = blockIdx.x * 16;
    float acc[8];
#pragma unroll
    for (int r = 0; r < 8; r++) acc[r] = 0.f;
    for (int kc = 0; kc < K; kc += 64) {
        float breg[64];
#pragma unroll
        for (int k = 0; k < 64; k++) breg[k] = B[(size_t)(kc + k) * 128 + col];
#pragma unroll
        for (int r = 0; r < 8; r++) {
            int row = rowBase + r * 2 + half;
            const float4* a4 = (const float4*)(A + (size_t)row * K + kc);
            float s = 0.f;
#pragma unroll
            for (int k4 = 0; k4 < 16; k4++) {
                float4 a = a4[k4];
                s += a.x * breg[4 * k4 + 0];
                s += a.y * breg[4 * k4 + 1];
                s += a.z * breg[4 * k4 + 2];
                s += a.w * breg[4 * k4 + 3];
            }
            acc[r] += s;
        }
    }
#pragma unroll
    for (int r = 0; r < 8; r++)
        C[(size_t)(rowBase + r * 2 + half) * 128 + col] = acc[r];
}

// ---------------- layernorm + relu -> F1, + partial sn2 (cols 128..255 of p2) ------
__global__ void k_ln_relu(const float* __restrict__ in, const float* __restrict__ g,
                          const float* __restrict__ b, const float* __restrict__ p2,
                          float* __restrict__ out) {
    int w = (blockIdx.x * blockDim.x + threadIdx.x) >> 5;   // row
    int lane = threadIdx.x & 31;
    if (w >= N_NODES) return;
    float v[4];
    float sum = 0.f;
#pragma unroll
    for (int i = 0; i < 4; i++) {
        v[i] = in[(size_t)w * 128 + lane + 32 * i];
        sum += v[i];
    }
    for (int o = 16; o; o >>= 1) sum += __shfl_xor_sync(0xffffffffu, sum, o);
    float mean = sum * (1.f / 128.f);
    float var = 0.f;
#pragma unroll
    for (int i = 0; i < 4; i++) { float d = v[i] - mean; var += d * d; }
    for (int o = 16; o; o >>= 1) var += __shfl_xor_sync(0xffffffffu, var, o);
    float rstd = rsqrtf(var * (1.f / 128.f) + 1e-5f);
    float dotp = 0.f;
#pragma unroll
    for (int i = 0; i < 4; i++) {
        int idx = lane + 32 * i;
        float y = (v[i] - mean) * rstd * g[idx] + b[idx];
        y = fmaxf(y, 0.f);
        out[(size_t)w * 256 + idx] = y;
        dotp += y * p2[128 + idx];
    }
    for (int o = 16; o; o >>= 1) dotp += __shfl_xor_sync(0xffffffffu, dotp, o);
    if (lane == 0) atomicAdd(&g_sn2[w], dotp);
}

// ---------------- fused edge MLP (layer 2) + se1 + partial se3 ----------------
__global__ void k_edge_mlp2(const float* __restrict__ Z, const float* __restrict__ W2,
                            const float* __restrict__ Wf2, const float* __restrict__ g2,
                            const float* __restrict__ be2, const float* __restrict__ p1,
                            const float* __restrict__ p3,
                            float* __restrict__ Yh, float* __restrict__ Z2F2) {
    __shared__ float sW[256], sF[256];
    int tid = threadIdx.x;
    sW[tid] = W2[tid];
    sF[tid] = Wf2[tid];
    __syncthreads();
    int c = tid & 15;
    int r = blockIdx.x * 16 + (tid >> 4);
    float zc = Z[(size_t)r * 16 + c];
    float a1 = 0.f, a2 = 0.f;
#pragma unroll
    for (int k = 0; k < 16; k++) {
        float zk = __shfl_sync(0xffffffffu, zc, k, 16);
        a1 += fmaxf(zk, 0.f) * sW[k * 16 + c];
        a2 += zk * sF[k * 16 + c];
    }
    Yh[(size_t)r * 16 + c] = a1;
    float d1 = zc * p1[c];
    for (int o = 8; o; o >>= 1) d1 += __shfl_xor_sync(0xffffffffu, d1, o, 16);
    if (c == 0) g_se1[r] = d1;
    float sum = a2;
    for (int o = 8; o; o >>= 1) sum += __shfl_xor_sync(0xffffffffu, sum, o, 16);
    float mean = sum * (1.f / 16.f);
    float d = a2 - mean;
    float var = d * d;
    for (int o = 8; o; o >>= 1) var += __shfl_xor_sync(0xffffffffu, var, o, 16);
    float rstd = rsqrtf(var * (1.f / 16.f) + 1e-5f);
    float y = fmaxf(d * rstd * g2[c] + be2[c], 0.f);
    Z2F2[(size_t)r * 32 + 16 + c] = y;
    float d3 = y * p3[16 + c];
    for (int o = 8; o; o >>= 1) d3 += __shfl_xor_sync(0xffffffffu, d3, o, 16);
    if (c == 0) atomicAdd(&g_se3[r], d3);
}

// ---------------- edge MLP (layer 4): Yh = Z2F2[E,32] @ W4[32,16] ----------------
__global__ void k_edge_mlp4(const float* __restrict__ A, const float* __restrict__ W4,
                            float* __restrict__ Yh) {
    __shared__ float sW[512];
    int tid = threadIdx.x;
    sW[(tid >> 4) * 16 + (tid & 15)] = W4[tid];
    sW[(16 + (tid >> 4)) * 16 + (tid & 15)] = W4[256 + tid];
    __syncthreads();
    int c = tid & 15;
    int r = blockIdx.x * 16 + (tid >> 4);
    float z0 = A[(size_t)r * 32 + c];
    float z1 = A[(size_t)r * 32 + 16 + c];
    float a = 0.f;
#pragma unroll
    for (int k = 0; k < 16; k++) {
        a += __shfl_sync(0xffffffffu, z0, k, 16) * sW[k * 16 + c];
        a += __shfl_sync(0xffffffffu, z1, k, 16) * sW[(16 + k) * 16 + c];
    }
    Yh[(size_t)r * 16 + c] = a;
}

// ---------------- node SpMM: two-phase (smem-staged structure) ----------------
__global__ void k_node_spmm(const float* __restrict__ Y, const float* __restrict__ bias,
                            const float* __restrict__ se, float* __restrict__ out,
                            int ldo, int do_relu,
                            const float* __restrict__ pgate, float* __restrict__ snOut) {
    __shared__ float s_mv[2][ELLW];
    __shared__ int   s_col[2][ELLW];
    int tid = threadIdx.x;
    int half = tid >> 7;
    int row = blockIdx.x * 2 + half;
    int n = g_vn[row]; if (n > ELLW) n = ELLW;
    int base = row * ELLW;
    if (((tid >> 5) & 3) == 0) {
        int lane = tid & 31;
        for (int i = lane; i < n; i += 32) {
            int col = g_vcol[base + i];
            float val = g_vval[base + i];
            float mult;
            if (col == row) {
                mult = 1.f;
            } else {
                int cnt = g_scnt[base + i];
                if (cnt > MAXPAR) cnt = MAXPAR;
                mult = 0.f;
#pragma unroll
                for (int q = 0; q < MAXPAR; q++)
                    if (q < cnt) mult += se[g_eid[(base + i) * MAXPAR + q]];
            }
            s_col[half][i] = col;
            s_mv[half][i] = val * mult;
        }
    }
    __syncthreads();
    int c = tid & 127;
    float acc = bias[c];
    for (int i = 0; i < n; i++)
        acc += s_mv[half][i] * Y[(size_t)s_col[half][i] * NH + c];
    if (do_relu) acc = fmaxf(acc, 0.f);
    out[(size_t)row * ldo + c] = acc;
    if (pgate) {
        float dp = acc * pgate[c];
        for (int o = 16; o; o >>= 1) dp += __shfl_xor_sync(0xffffffffu, dp, o);
        if ((tid & 31) == 0) atomicAdd(&snOut[row], dp);
    }
}

// ---------------- edge SpMM: two-phase (smem-staged weights) ----------------
__global__ void k_edge_spmm(const float* __restrict__ Yh, const float* __restrict__ bias,
                            const unsigned* __restrict__ cmax, float* __restrict__ out,
                            int ldo, const float* __restrict__ p, float* __restrict__ seOut,
                            int gmode) {
    __shared__ float s_w[16][ELLW];
    __shared__ int   s_f[16][ELLW];
    int tid = threadIdx.x;
    int rl = tid >> 4;          // local row 0..15
    int c = tid & 15;
    int r = blockIdx.x * 16 + rl;
    int n = g_en[r]; if (n > ELLW) n = ELLW;
    size_t base = (size_t)r * ELLW;
    for (int i = c; i < n; i += 16) {
        int f = g_ecol[base + i];
        s_f[rl][i] = f;
        s_w[rl][i] = g_adjEv[base + i] / __uint_as_float(cmax[f]);
    }
    __syncthreads();
    float acc = bias[c];
    for (int i = 0; i < n; i++)
        acc += s_w[rl][i] * Yh[(size_t)s_f[rl][i] * FE + c];
    acc = fmaxf(acc, 0.f);
    out[(size_t)r * ldo + c] = acc;
    if (gmode) {
        float dp = acc * p[c];
        for (int o = 8; o; o >>= 1) dp += __shfl_xor_sync(0xffffffffu, dp, o, 16);
        if (c == 0) {
            if (gmode == 1) atomicAdd(&seOut[r], dp);
            else            seOut[r] = dp;
        }
    }
}

// ---------------- host ----------------
extern "C" void kernel_launch(void* const* d_in, const int* in_sizes, int n_in,
                              void* d_out, int out_size) {
    const float* X    = (const float*)d_in[0];
    const float* Z    = (const float*)d_in[1];
    const float* adjE = (const float*)d_in[2];
    const float* adjV = (const float*)d_in[3];
    const float* T    = (const float*)d_in[4];
    const float* W1  = (const float*)d_in[5];
    const float* p1  = (const float*)d_in[6];
    const float* b1  = (const float*)d_in[7];
    const float* Wf1 = (const float*)d_in[8];
    const float* g1  = (const float*)d_in[9];
    const float* be1 = (const float*)d_in[10];
    const float* W2  = (const float*)d_in[11];
    const float* p2  = (const float*)d_in[12];
    const float* b2  = (const float*)d_in[13];
    const float* Wf2 = (const float*)d_in[14];
    const float* g2  = (const float*)d_in[15];
    const float* be2 = (const float*)d_in[16];
    const float* W3  = (const float*)d_in[17];
    const float* p3  = (const float*)d_in[18];
    const float* b3  = (const float*)d_in[19];
    const float* W4  = (const float*)d_in[20];
    const float* p4  = (const float*)d_in[21];
    const float* b4  = (const float*)d_in[22];
    const float* W5  = (const float*)d_in[23];
    const float* p5  = (const float*)d_in[24];
    const float* b5  = (const float*)d_in[25];
    float* out = (float*)d_out;

    float *pY, *ptmpN, *pX1F1, *pX3, *pYh, *pZ2F2, *pZ4;
    float *pse1, *pse3, *pse5, *psn2, *psn4;
    unsigned *pcm2, *pcm4;
    cudaGetSymbolAddress((void**)&pY, g_Y);
    cudaGetSymbolAddress((void**)&ptmpN, g_tmpN);
    cudaGetSymbolAddress((void**)&pX1F1, g_X1F1);
    cudaGetSymbolAddress((void**)&pX3, g_X3);
    cudaGetSymbolAddress((void**)&pYh, g_Yh);
    cudaGetSymbolAddress((void**)&pZ2F2, g_Z2F2);
    cudaGetSymbolAddress((void**)&pZ4, g_Z4);
    cudaGetSymbolAddress((void**)&pse1, g_se1);
    cudaGetSymbolAddress((void**)&pse3, g_se3);
    cudaGetSymbolAddress((void**)&pse5, g_se5);
    cudaGetSymbolAddress((void**)&psn2, g_sn2);
    cudaGetSymbolAddress((void**)&psn4, g_sn4);
    cudaGetSymbolAddress((void**)&pcm2, g_cmax2);
    cudaGetSymbolAddress((void**)&pcm4, g_cmax4);

    // one-time side stream + events (created on first, uncaptured, correctness call)
    static cudaStream_t sB = 0;
    static cudaEvent_t evInit = 0, evFront = 0, evSpmm1 = 0, evGemm3 = 0,
                       evSpmm3 = 0, evGemm5 = 0;
    if (!sB) {
        cudaStreamCreateWithFlags(&sB, cudaStreamNonBlocking);
        cudaEventCreateWithFlags(&evInit,  cudaEventDisableTiming);
        cudaEventCreateWithFlags(&evFront, cudaEventDisableTiming);
        cudaEventCreateWithFlags(&evSpmm1, cudaEventDisableTiming);
        cudaEventCreateWithFlags(&evGemm3, cudaEventDisableTiming);
        cudaEventCreateWithFlags(&evSpmm3, cudaEventDisableTiming);
        cudaEventCreateWithFlags(&evGemm5, cudaEventDisableTiming);
    }

    // ---- init on main stream; fork dense front to sB, scan on main ----
    k_init<<<348, 256>>>();
    cudaEventRecord(evInit, 0);
    cudaStreamWaitEvent(sB, evInit, 0);

    // branch B: dense front (independent of structure scan)
    k_edge_mlp2<<<256, 256, 0, sB>>>(Z, W2, Wf2, g2, be2, p1, p3, pYh, pZ2F2);
    k_gemmRB<<<dim3(128, 2), 256, 0, sB>>>(X, W1, Wf1, pY, ptmpN, FV);
    k_ln_relu<<<256, 256, 0, sB>>>(ptmpN, g1, be1, p2, pX1F1 + NH);
    cudaEventRecord(evFront, sB);

    // branch A (main): structure scan + link/coefs
    k_scan_all<<<2048, 256>>>((const float4*)T, (const float4*)adjV, (const float4*)adjE);
    k_link_ecoef<<<16, 256>>>();

    // join: layer-1 node spmm needs scan+link (A) and Y/se1/sn2 (B)
    cudaStreamWaitEvent(0, evFront, 0);
    k_node_spmm<<<1024, 256>>>(pY, b1, pse1, pX1F1, 2 * NH, 1, p2, psn2);
    cudaEventRecord(evSpmm1, 0);

    // fork: gemm3 (B) || vals2 -> spmm2 -> mlp4 (A)
    cudaStreamWaitEvent(sB, evSpmm1, 0);
    k_gemmRB<<<dim3(128, 1), 256, 0, sB>>>(pX1F1, W3, W3, ptmpN, ptmpN, 2 * NH);
    cudaEventRecord(evGemm3, sB);

    k_edge_vals<<<640, 256>>>(psn2, pcm2);
    k_edge_spmm<<<256, 256>>>(pYh, b2, pcm2, pZ2F2, 2 * FE, p3, pse3, 1);
    k_edge_mlp4<<<256, 256>>>(pZ2F2, W4, pYh);

    // join: spmm3 needs tmpN (gemm3) + se3 (mlp2 + spmm2)
    cudaStreamWaitEvent(0, evGemm3, 0);
    k_node_spmm<<<1024, 256>>>(ptmpN, b3, pse3, pX3, NH, 1, p4, psn4);
    cudaEventRecord(evSpmm3, 0);

    // fork: gemm5 (B, must be after spmm3's read of tmpN) || vals4 -> spmm4 (A)
    cudaStreamWaitEvent(sB, evSpmm3, 0);
    k_gemmRB<<<dim3(128, 1), 256, 0, sB>>>(pX3, W5, W5, ptmpN, ptmpN, NH);
    cudaEventRecord(evGemm5, sB);

    k_edge_vals<<<640, 256>>>(psn4, pcm4);
    k_edge_spmm<<<256, 256>>>(pYh, b4, pcm4, pZ4, FE, p5, pse5, 2);

    // join: final node spmm -> out
    cudaStreamWaitEvent(0, evGemm5, 0);
    k_node_spmm<<<1024, 256>>>(ptmpN, b5, pse5, out, NC, 0, (const float*)0, (float*)0);
}